// round 4
// baseline (speedup 1.0000x reference)
#include <cuda_runtime.h>
#include <math.h>

#define NN 10000
#define NE 160000
#define FD 128
#define NBASIS 8
#define NHID 64
#define NSPEC 10
#define NEB (NE/32)                  // 5000 edge-blocks of 32
#define PERM_SZ (NN + 16*NSPEC)
#define RMAXF 5.0f
#define PI_F 3.14159265358979323846f

// ---------------- device scratch (static, no allocations) ----------------
__device__ __align__(16) float g_h[2*NEB*NHID*32];  // h, blocked [l][eb][j][e] (82 MB)
__device__ __align__(16) float g_scal[NN*FD];       // node scalar features
__device__ __align__(16) float g_agg[NN*FD];        // aggregated messages
__device__ __align__(16) float g_w2t[2*NHID*FD];    // W2 l=0 cols, transposed
__device__ int   g_cnt[NSPEC];
__device__ int   g_cur[NSPEC];
__device__ int   g_off[NSPEC+1];
__device__ int   g_perm[PERM_SZ];

// ---------------- f32x2 / vector-red helpers --------------------------------
__device__ __forceinline__ unsigned long long dup2(float w){
    unsigned long long r; asm("mov.b64 %0, {%1, %1};" : "=l"(r) : "f"(w)); return r;
}
__device__ __forceinline__ void ffma2(unsigned long long& acc, unsigned long long a,
                                      unsigned long long b){
    asm("fma.rn.f32x2 %0, %1, %2, %0;" : "+l"(acc) : "l"(a), "l"(b));
}
__device__ __forceinline__ float2 unpk(unsigned long long v){
    float2 r; asm("mov.b64 {%0, %1}, %2;" : "=f"(r.x), "=f"(r.y) : "l"(v)); return r;
}
__device__ __forceinline__ void red4(float* p, float a, float b, float c, float d){
    asm volatile("red.global.add.v4.f32 [%0], {%1,%2,%3,%4};"
                 :: "l"(p), "f"(a), "f"(b), "f"(c), "f"(d) : "memory");
}

// ---------------- k_h: radial basis + hidden layer for BOTH layers ----------
// 128 threads = 4 warps; warp <-> 32-edge block; lane <-> edge.
__global__ __launch_bounds__(128) void k_h(
    const float* __restrict__ vec,
    const float* __restrict__ rW1, const float* __restrict__ rb1)
{
    __shared__ float W1s[2*NBASIS*NHID];
    __shared__ float b1s[2*NHID];
    int tid = threadIdx.x;
    for (int i = tid; i < 2*NBASIS*NHID; i += 128) W1s[i] = rW1[i];
    if (tid < 2*NHID) b1s[tid] = rb1[tid];
    if (blockIdx.x == 0 && tid < NSPEC){ g_cnt[tid] = 0; g_cur[tid] = 0; }
    __syncthreads();

    int lane = tid & 31, w = tid >> 5;
    int eb = blockIdx.x*4 + w;
    int e  = eb*32 + lane;

    float x = vec[3*e+0], y = vec[3*e+1], z = vec[3*e+2];
    float r = fmaxf(sqrtf(x*x + y*y + z*z), 1e-9f);
    float rc  = fminf(r, RMAXF);
    float cut = 0.5f*(__cosf(PI_F*rc/RMAXF) + 1.0f);
    float pref = sqrtf(2.0f/RMAXF) / r * cut;
    float arg = PI_F * r / RMAXF;
    float s1 = __sinf(arg), c2 = 2.0f*__cosf(arg);
    float rb[NBASIS];
    { float sm1 = 0.0f, s = s1;
      #pragma unroll
      for (int n = 0; n < NBASIS; n++){ rb[n] = pref*s; float sn = c2*s - sm1; sm1 = s; s = sn; } }

    #pragma unroll
    for (int l = 0; l < 2; l++){
        float* hp = g_h + ((size_t)(l*NEB + eb))*NHID*32 + lane;
        const float* W1l = W1s + l*NBASIS*NHID;
        const float* b1l = b1s + l*NHID;
        #pragma unroll 4
        for (int j = 0; j < NHID; j++){
            float a = b1l[j];
            #pragma unroll
            for (int k = 0; k < NBASIS; k++)
                a = fmaf(rb[k], W1l[k*NHID + j], a);
            hp[j*32] = __fdividef(a, 1.0f + __expf(-a));
        }
    }
}

// ---------------- init: scal = emb_W[specie]; agg = 0; species counts -------
__global__ void k_init(const int* __restrict__ spec, const float* __restrict__ emb){
    int idx = blockIdx.x*256 + threadIdx.x;
    if (idx >= NN*FD) return;
    int n = idx >> 7, f = idx & 127;
    int s = spec[n];
    g_scal[idx] = emb[s*FD + f];
    g_agg[idx]  = 0.0f;
    if (f == 0) atomicAdd(&g_cnt[s], 1);
}

// ---------------- W2 transpose + perm init -----------------------------------
__global__ void k_w2t(const float* __restrict__ W2){
    int idx = blockIdx.x*256 + threadIdx.x;
    if (idx < 2*NHID*FD){
        int l = idx >> 13, rem = idx & 8191;
        int j = rem >> 7, ch = rem & 127;
        g_w2t[idx] = W2[l*NHID*FD*4 + j*FD*4 + ch*4];
    }
    if (idx < PERM_SZ) g_perm[idx] = -1;
}

__global__ void k_b2(){
    if (threadIdx.x == 0){
        int o = 0;
        for (int s = 0; s < NSPEC; s++){ g_off[s] = o; o += (g_cnt[s] + 15) & ~15; }
        g_off[NSPEC] = o;
    }
}
__global__ void k_b4(const int* __restrict__ spec){
    int n = blockIdx.x*256 + threadIdx.x;
    if (n < NN){
        int s = spec[n];
        int p = atomicAdd(&g_cur[s], 1);
        g_perm[g_off[s] + p] = n;
    }
}

// ---------------- edge kernel: sync-free, smem-free ---------------------------
// 256 threads = 8 warps; warp = (eb-group half, ch-quarter). Each warp: 4 tiles
// of 32 edges x 32 ch. GEMM from L1-cached W2t + blocked g_h; red.v4 scatter.
__global__ __launch_bounds__(256, 3) void k_edge(
    const float* __restrict__ W2t,
    const int* __restrict__ snd, const int* __restrict__ rcv,
    const float* __restrict__ hbase)
{
    int tid = threadIdx.x, lane = tid & 31, w = tid >> 5;
    int g = lane & 3, cg = lane >> 2;
    int ch0 = (w & 3)*32 + cg*4;
    int ebgrp = blockIdx.x*8 + (w >> 2)*4;

    for (int t = 0; t < 4; t++){
        int eb = ebgrp + t;
        int e0 = eb*32;
        int sidx = snd[e0 + lane];
        int ridx = rcv[e0 + lane];
        const float* hp = hbase + (size_t)eb*NHID*32 + g*8;

        unsigned long long acc[4][4];
        #pragma unroll
        for (int c = 0; c < 4; c++)
            #pragma unroll
            for (int p = 0; p < 4; p++) acc[c][p] = 0ULL;

        #pragma unroll 4
        for (int j = 0; j < NHID; j++){
            float4 w4 = *(const float4*)(W2t + j*FD + ch0);
            unsigned long long wd0 = dup2(w4.x), wd1 = dup2(w4.y);
            unsigned long long wd2 = dup2(w4.z), wd3 = dup2(w4.w);
            ulonglong2 ha = *(const ulonglong2*)(hp + j*32);
            ulonglong2 hb = *(const ulonglong2*)(hp + j*32 + 4);
            ffma2(acc[0][0], ha.x, wd0); ffma2(acc[0][1], ha.y, wd0);
            ffma2(acc[0][2], hb.x, wd0); ffma2(acc[0][3], hb.y, wd0);
            ffma2(acc[1][0], ha.x, wd1); ffma2(acc[1][1], ha.y, wd1);
            ffma2(acc[1][2], hb.x, wd1); ffma2(acc[1][3], hb.y, wd1);
            ffma2(acc[2][0], ha.x, wd2); ffma2(acc[2][1], ha.y, wd2);
            ffma2(acc[2][2], hb.x, wd2); ffma2(acc[2][3], hb.y, wd2);
            ffma2(acc[3][0], ha.x, wd3); ffma2(acc[3][1], ha.y, wd3);
            ffma2(acc[3][2], hb.x, wd3); ffma2(acc[3][3], hb.y, wd3);
        }

        #pragma unroll
        for (int p = 0; p < 4; p++){
            int ea = g*8 + 2*p, ebx = ea + 1;
            int sa = __shfl_sync(0xffffffffu, sidx, ea);
            int ra = __shfl_sync(0xffffffffu, ridx, ea);
            int sb = __shfl_sync(0xffffffffu, sidx, ebx);
            int rb2 = __shfl_sync(0xffffffffu, ridx, ebx);
            float2 m0 = unpk(acc[0][p]);
            float2 m1 = unpk(acc[1][p]);
            float2 m2 = unpk(acc[2][p]);
            float2 m3 = unpk(acc[3][p]);
            float4 ssa = *(const float4*)&g_scal[sa*FD + ch0];
            float4 ssb = *(const float4*)&g_scal[sb*FD + ch0];
            red4(&g_agg[ra*FD + ch0],
                 m0.x*ssa.x, m1.x*ssa.y, m2.x*ssa.z, m3.x*ssa.w);
            red4(&g_agg[rb2*FD + ch0],
                 m0.y*ssb.x, m1.y*ssb.y, m2.y*ssb.z, m3.y*ssb.w);
        }
    }
}

// ---------------- fused node kernel: lin (l=0) + sc (l=0) + poly ------------
// ZERO_AGG: layer-0 variant also clears g_agg rows after reading them.
template<bool HAS_SC>
__global__ __launch_bounds__(128) void k_node(
    const float* __restrict__ linW,
    const float* __restrict__ scWp,
    const float* __restrict__ pc)
{
    int tid = threadIdx.x;
    int c16 = blockIdx.x * 16;
    if (c16 >= g_off[NSPEC]) return;
    int s = 0;
    while (c16 >= g_off[s+1]) s++;

    __shared__ int   nodes[16];
    __shared__ float Wl[16*FD];
    __shared__ float Ws[16*FD];
    __shared__ float Aa[16*16];
    __shared__ float As[16*16];
    if (tid < 16) nodes[tid] = g_perm[c16 + tid];

    float aU[16], aV[16];
    #pragma unroll
    for (int r = 0; r < 16; r++){ aU[r] = 0.0f; aV[r] = 0.0f; }

    const float* WL = linW + (size_t)s * 4 * FD * FD;
    const float* WS = HAS_SC ? (scWp + (size_t)s * 4 * FD * FD) : linW;

    for (int ft0 = 0; ft0 < FD; ft0 += 16){
        __syncthreads();
        for (int i = tid; i < 16*FD; i += 128){
            int r = i >> 7, gg = i & 127;
            Wl[i] = WL[(ft0 + r)*FD + gg];
            if (HAS_SC) Ws[i] = WS[(ft0 + r)*FD + gg];
        }
        for (int i = tid; i < 256; i += 128){
            int r = i >> 4, nd = nodes[r];
            int fc = ft0 + (i & 15);
            Aa[i] = (nd < 0) ? 0.0f : g_agg[nd*FD + fc];
            if (HAS_SC) As[i] = (nd < 0) ? 0.0f : g_scal[nd*FD + fc];
        }
        __syncthreads();
        for (int ft = 0; ft < 16; ft++){
            float wl = Wl[ft*FD + tid];
            float ws = HAS_SC ? Ws[ft*FD + tid] : 0.0f;
            #pragma unroll
            for (int r = 0; r < 16; r++){
                aU[r] = fmaf(Aa[r*16 + ft], wl, aU[r]);
                if (HAS_SC) aV[r] = fmaf(As[r*16 + ft], ws, aV[r]);
            }
        }
    }
    const float* C = pc + s*3*FD;
    float c0 = C[tid], c1 = C[FD + tid], c2 = C[2*FD + tid];
    #pragma unroll
    for (int r = 0; r < 16; r++){
        int nd = nodes[r];
        if (nd < 0) continue;
        float sv = 0.5f * aU[r];
        float o  = sv * (c0 + c1*sv + c2*sv*sv);
        if (HAS_SC) o += aV[r];
        g_scal[nd*FD + tid] = o;
        if (!HAS_SC) g_agg[nd*FD + tid] = 0.0f;   // prep for layer 1
    }
}

// ---------------- readouts ---------------------------------------------------
__global__ void k_ro0(const float* __restrict__ ro0, float* __restrict__ out){
    int w = (blockIdx.x*blockDim.x + threadIdx.x) >> 5;
    int lane = threadIdx.x & 31;
    if (w >= NN) return;
    float sacc = 0.0f;
    #pragma unroll
    for (int k = 0; k < 4; k++){
        int f = lane + 32*k;
        sacc = fmaf(g_scal[w*FD + f], ro0[f], sacc);
    }
    #pragma unroll
    for (int o = 16; o; o >>= 1) sacc += __shfl_xor_sync(0xffffffffu, sacc, o);
    if (lane == 0) out[w*2 + 0] = sacc;
}

__global__ void k_ro1(const float* __restrict__ W1, const float* __restrict__ W2,
                      float* __restrict__ out){
    int w = (blockIdx.x*blockDim.x + threadIdx.x) >> 5;
    int lane = threadIdx.x & 31;
    if (w >= NN) return;
    float sc[4];
    #pragma unroll
    for (int k = 0; k < 4; k++) sc[k] = g_scal[w*FD + lane + 32*k];
    float acc = 0.0f;
    #pragma unroll
    for (int j = 0; j < 16; j++){
        float p = 0.0f;
        #pragma unroll
        for (int k = 0; k < 4; k++)
            p = fmaf(sc[k], W1[(lane + 32*k)*16 + j], p);
        #pragma unroll
        for (int o = 16; o; o >>= 1) p += __shfl_xor_sync(0xffffffffu, p, o);
        float h = __fdividef(p, 1.0f + __expf(-p));
        acc = fmaf(h, W2[j], acc);
    }
    if (lane == 0) out[w*2 + 1] = acc;
}

// ---------------- launcher ---------------------------------------------------
extern "C" void kernel_launch(void* const* d_in, const int* in_sizes, int n_in,
                              void* d_out, int out_size)
{
    const float* vectors = (const float*)d_in[0];
    const int*   spec    = (const int*)  d_in[1];
    const int*   snd     = (const int*)  d_in[2];
    const int*   rcv     = (const int*)  d_in[3];
    const float* emb     = (const float*)d_in[4];
    const float* rW1     = (const float*)d_in[5];
    const float* rb1     = (const float*)d_in[6];
    const float* rW2     = (const float*)d_in[7];
    const float* linW    = (const float*)d_in[8];
    const float* pc      = (const float*)d_in[9];
    const float* scW     = (const float*)d_in[10];
    const float* ro0     = (const float*)d_in[11];
    const float* ro1W1   = (const float*)d_in[12];
    const float* ro1W2   = (const float*)d_in[13];
    float* out = (float*)d_out;

    const int LAYER_LIN  = NSPEC * 4 * FD * FD;
    const int LAYER_PC   = NSPEC * 3 * FD;

    float* w2t_ptr;  cudaGetSymbolAddress((void**)&w2t_ptr, g_w2t);
    float* h_ptr;    cudaGetSymbolAddress((void**)&h_ptr,   g_h);

    int nchunks = NN/16 + NSPEC;

    k_h<<<NEB/4, 128>>>(vectors, rW1, rb1);                          // 1
    k_init<<<(NN*FD + 255)/256, 256>>>(spec, emb);                   // 2
    k_w2t<<<64, 256>>>(rW2);                                         // 3
    k_edge<<<NE/256, 256>>>(w2t_ptr, snd, rcv, h_ptr);               // 4  layer 0 (profiled)
    k_b2<<<1, 32>>>();                                               // 5
    k_b4<<<(NN + 255)/256, 256>>>(spec);                             // 6
    k_node<false><<<nchunks, 128>>>(linW, linW, pc);                 // 7 (+agg zero)
    k_ro0<<<(NN*32 + 255)/256, 256>>>(ro0, out);                     // 8
    k_edge<<<NE/256, 256>>>(w2t_ptr + NHID*FD, snd, rcv,
                            h_ptr + (size_t)NEB*NHID*32);            // 9  layer 1
    k_node<true><<<nchunks, 128>>>(linW + LAYER_LIN, scW + LAYER_LIN,
                                   pc + LAYER_PC);                   // 10
    k_ro1<<<(NN*32 + 255)/256, 256>>>(ro1W1, ro1W2, out);            // 11
}

// round 5
// speedup vs baseline: 1.0468x; 1.0468x over previous
#include <cuda_runtime.h>
#include <math.h>

#define NN 10000
#define NE 160000
#define FD 128
#define NBASIS 8
#define NHID 64
#define NSPEC 10
#define NEB (NE/32)                  // 5000 edge-blocks of 32
#define PERM_SZ (NN + 16*NSPEC)
#define RMAXF 5.0f
#define PI_F 3.14159265358979323846f

typedef unsigned long long ull;

// ---------------- device scratch (static, no allocations) ----------------
__device__ __align__(16) float g_h[2*NEB*NHID*32];  // h, blocked [l][eb][j][e]
__device__ __align__(16) float g_scal[NN*FD];       // node scalar features
__device__ __align__(16) float g_agg[NN*FD];        // aggregated messages
__device__ __align__(16) ull   g_w2d[2*NHID*FD];    // W2 l=0 cols, dup'd f32x2
__device__ int   g_cnt[NSPEC];
__device__ int   g_cur[NSPEC];
__device__ int   g_off[NSPEC+1];
__device__ int   g_perm[PERM_SZ];

// ---------------- f32x2 / vector-red helpers --------------------------------
__device__ __forceinline__ ull dup2(float w){
    ull r; asm("mov.b64 %0, {%1, %1};" : "=l"(r) : "f"(w)); return r;
}
__device__ __forceinline__ void ffma2(ull& acc, ull a, ull b){
    asm("fma.rn.f32x2 %0, %1, %2, %0;" : "+l"(acc) : "l"(a), "l"(b));
}
__device__ __forceinline__ float2 unpk(ull v){
    float2 r; asm("mov.b64 {%0, %1}, %2;" : "=f"(r.x), "=f"(r.y) : "l"(v)); return r;
}
__device__ __forceinline__ void red4(float* p, float a, float b, float c, float d){
    asm volatile("red.global.add.v4.f32 [%0], {%1,%2,%3,%4};"
                 :: "l"(p), "f"(a), "f"(b), "f"(c), "f"(d) : "memory");
}
__device__ __forceinline__ void cpasync16(unsigned dst, const void* src){
    asm volatile("cp.async.cg.shared.global [%0], [%1], 16;" :: "r"(dst), "l"(src));
}

// ---------------- k_h: radial basis + hidden layer for BOTH layers ----------
__global__ __launch_bounds__(128) void k_h(
    const float* __restrict__ vec,
    const float* __restrict__ rW1, const float* __restrict__ rb1)
{
    __shared__ float W1s[2*NBASIS*NHID];
    __shared__ float b1s[2*NHID];
    int tid = threadIdx.x;
    for (int i = tid; i < 2*NBASIS*NHID; i += 128) W1s[i] = rW1[i];
    if (tid < 2*NHID) b1s[tid] = rb1[tid];
    if (blockIdx.x == 0 && tid < NSPEC){ g_cnt[tid] = 0; g_cur[tid] = 0; }
    __syncthreads();

    int lane = tid & 31, w = tid >> 5;
    int eb = blockIdx.x*4 + w;
    int e  = eb*32 + lane;

    float x = vec[3*e+0], y = vec[3*e+1], z = vec[3*e+2];
    float r = fmaxf(sqrtf(x*x + y*y + z*z), 1e-9f);
    float rc  = fminf(r, RMAXF);
    float cut = 0.5f*(__cosf(PI_F*rc/RMAXF) + 1.0f);
    float pref = sqrtf(2.0f/RMAXF) / r * cut;
    float arg = PI_F * r / RMAXF;
    float s1 = __sinf(arg), c2 = 2.0f*__cosf(arg);
    float rb[NBASIS];
    { float sm1 = 0.0f, s = s1;
      #pragma unroll
      for (int n = 0; n < NBASIS; n++){ rb[n] = pref*s; float sn = c2*s - sm1; sm1 = s; s = sn; } }

    #pragma unroll
    for (int l = 0; l < 2; l++){
        float* hp = g_h + ((size_t)(l*NEB + eb))*NHID*32 + lane;
        const float* W1l = W1s + l*NBASIS*NHID;
        const float* b1l = b1s + l*NHID;
        #pragma unroll 4
        for (int j = 0; j < NHID; j++){
            float a = b1l[j];
            #pragma unroll
            for (int k = 0; k < NBASIS; k++)
                a = fmaf(rb[k], W1l[k*NHID + j], a);
            hp[j*32] = __fdividef(a, 1.0f + __expf(-a));
        }
    }
}

// ---------------- init: scal = emb_W[specie]; agg = 0; species counts -------
__global__ void k_init(const int* __restrict__ spec, const float* __restrict__ emb){
    int idx = blockIdx.x*256 + threadIdx.x;
    if (idx >= NN*FD) return;
    int n = idx >> 7, f = idx & 127;
    int s = spec[n];
    g_scal[idx] = emb[s*FD + f];
    g_agg[idx]  = 0.0f;
    if (f == 0) atomicAdd(&g_cnt[s], 1);
}

// ---------------- W2 dup-transpose + perm init --------------------------------
__global__ void k_w2t(const float* __restrict__ W2){
    int idx = blockIdx.x*256 + threadIdx.x;
    if (idx < 2*NHID*FD){
        int l = idx >> 13, rem = idx & 8191;
        int j = rem >> 7, ch = rem & 127;
        g_w2d[idx] = dup2(W2[l*NHID*FD*4 + j*FD*4 + ch*4]);
    }
    if (idx < PERM_SZ) g_perm[idx] = -1;
}

__global__ void k_b2(){
    if (threadIdx.x == 0){
        int o = 0;
        for (int s = 0; s < NSPEC; s++){ g_off[s] = o; o += (g_cnt[s] + 15) & ~15; }
        g_off[NSPEC] = o;
    }
}
__global__ void k_b4(const int* __restrict__ spec){
    int n = blockIdx.x*256 + threadIdx.x;
    if (n < NN){
        int s = spec[n];
        int p = atomicAdd(&g_cur[s], 1);
        g_perm[g_off[s] + p] = n;
    }
}

// ---------------- edge kernel: cp.async-pipelined register GEMM --------------
// 256 threads = 8 warps = (2 edge-halves) x (4 ch-quarters). Block processes
// 8 ebs (256 edges) as 4 chunks of 2 ebs. h streamed into a 3-buffer smem ring
// by cp.async; W2 (dup'd f32x2) read via L1-resident LDG. One sync per chunk.
__global__ __launch_bounds__(256) void k_edge(
    const ull* __restrict__ W2d,
    const int* __restrict__ snd, const int* __restrict__ rcv,
    const float* __restrict__ hbase)
{
    __shared__ float h_s[3][2][NHID][32];     // 48 KB ring
    int tid = threadIdx.x, lane = tid & 31, w = tid >> 5;
    int g = lane & 3, cg = lane >> 2;
    int ch0 = (w & 3)*32 + cg*4;
    int ehalf = w >> 2;
    int eb0 = blockIdx.x * 8;

    unsigned sb = (unsigned)__cvta_generic_to_shared(&h_s[0][0][0][0]);

    // prologue: stage chunks 0,1
    #pragma unroll
    for (int c = 0; c < 2; c++){
        const float* src = hbase + (size_t)(eb0 + c*2)*NHID*32;
        unsigned dst = sb + c*16384;
        #pragma unroll
        for (int q = 0; q < 4; q++)
            cpasync16(dst + (tid + q*256)*16, src + (tid + q*256)*4);
        asm volatile("cp.async.commit_group;");
    }

    #pragma unroll
    for (int c = 0; c < 4; c++){
        asm volatile("cp.async.wait_group 1;");
        __syncthreads();
        if (c + 2 < 4){
            const float* src = hbase + (size_t)(eb0 + (c+2)*2)*NHID*32;
            unsigned dst = sb + ((c+2)%3)*16384;
            #pragma unroll
            for (int q = 0; q < 4; q++)
                cpasync16(dst + (tid + q*256)*16, src + (tid + q*256)*4);
        }
        asm volatile("cp.async.commit_group;");   // empty group on tail iters

        int eb = eb0 + c*2 + ehalf;
        int e0 = eb*32;
        int sidx = snd[e0 + lane];
        int ridx = rcv[e0 + lane];
        const float* hp = &h_s[c%3][ehalf][0][0] + g*8;
        const ull* wp = W2d + ch0;

        ull acc[4][4];
        #pragma unroll
        for (int cc = 0; cc < 4; cc++)
            #pragma unroll
            for (int p = 0; p < 4; p++) acc[cc][p] = 0ULL;

        #pragma unroll 4
        for (int j = 0; j < NHID; j++){
            ulonglong2 wa = *(const ulonglong2*)(wp + j*FD);
            ulonglong2 wb = *(const ulonglong2*)(wp + j*FD + 2);
            ulonglong2 ha = *(const ulonglong2*)(hp + j*32);
            ulonglong2 hb = *(const ulonglong2*)(hp + j*32 + 4);
            ffma2(acc[0][0], ha.x, wa.x); ffma2(acc[0][1], ha.y, wa.x);
            ffma2(acc[0][2], hb.x, wa.x); ffma2(acc[0][3], hb.y, wa.x);
            ffma2(acc[1][0], ha.x, wa.y); ffma2(acc[1][1], ha.y, wa.y);
            ffma2(acc[1][2], hb.x, wa.y); ffma2(acc[1][3], hb.y, wa.y);
            ffma2(acc[2][0], ha.x, wb.x); ffma2(acc[2][1], ha.y, wb.x);
            ffma2(acc[2][2], hb.x, wb.x); ffma2(acc[2][3], hb.y, wb.x);
            ffma2(acc[3][0], ha.x, wb.y); ffma2(acc[3][1], ha.y, wb.y);
            ffma2(acc[3][2], hb.x, wb.y); ffma2(acc[3][3], hb.y, wb.y);
        }

        #pragma unroll
        for (int p = 0; p < 4; p++){
            int ea = g*8 + 2*p, ebx = ea + 1;
            int sa  = __shfl_sync(0xffffffffu, sidx, ea);
            int ra  = __shfl_sync(0xffffffffu, ridx, ea);
            int sbx = __shfl_sync(0xffffffffu, sidx, ebx);
            int rbx = __shfl_sync(0xffffffffu, ridx, ebx);
            float2 m0 = unpk(acc[0][p]);
            float2 m1 = unpk(acc[1][p]);
            float2 m2 = unpk(acc[2][p]);
            float2 m3 = unpk(acc[3][p]);
            float4 ssa = *(const float4*)&g_scal[sa*FD + ch0];
            float4 ssb = *(const float4*)&g_scal[sbx*FD + ch0];
            red4(&g_agg[ra*FD + ch0],
                 m0.x*ssa.x, m1.x*ssa.y, m2.x*ssa.z, m3.x*ssa.w);
            red4(&g_agg[rbx*FD + ch0],
                 m0.y*ssb.x, m1.y*ssb.y, m2.y*ssb.z, m3.y*ssb.w);
        }
    }
}

// ---------------- fused node kernel: lin (l=0) + sc (l=0) + poly ------------
template<bool HAS_SC>
__global__ __launch_bounds__(128) void k_node(
    const float* __restrict__ linW,
    const float* __restrict__ scWp,
    const float* __restrict__ pc)
{
    int tid = threadIdx.x;
    int c16 = blockIdx.x * 16;
    if (c16 >= g_off[NSPEC]) return;
    int s = 0;
    while (c16 >= g_off[s+1]) s++;

    __shared__ int   nodes[16];
    __shared__ float Wl[16*FD];
    __shared__ float Ws[16*FD];
    __shared__ float Aa[16*16];
    __shared__ float As[16*16];
    if (tid < 16) nodes[tid] = g_perm[c16 + tid];

    float aU[16], aV[16];
    #pragma unroll
    for (int r = 0; r < 16; r++){ aU[r] = 0.0f; aV[r] = 0.0f; }

    const float* WL = linW + (size_t)s * 4 * FD * FD;
    const float* WS = HAS_SC ? (scWp + (size_t)s * 4 * FD * FD) : linW;

    for (int ft0 = 0; ft0 < FD; ft0 += 16){
        __syncthreads();
        for (int i = tid; i < 16*FD; i += 128){
            int r = i >> 7, gg = i & 127;
            Wl[i] = WL[(ft0 + r)*FD + gg];
            if (HAS_SC) Ws[i] = WS[(ft0 + r)*FD + gg];
        }
        for (int i = tid; i < 256; i += 128){
            int r = i >> 4, nd = nodes[r];
            int fc = ft0 + (i & 15);
            Aa[i] = (nd < 0) ? 0.0f : g_agg[nd*FD + fc];
            if (HAS_SC) As[i] = (nd < 0) ? 0.0f : g_scal[nd*FD + fc];
        }
        __syncthreads();
        for (int ft = 0; ft < 16; ft++){
            float wl = Wl[ft*FD + tid];
            float ws = HAS_SC ? Ws[ft*FD + tid] : 0.0f;
            #pragma unroll
            for (int r = 0; r < 16; r++){
                aU[r] = fmaf(Aa[r*16 + ft], wl, aU[r]);
                if (HAS_SC) aV[r] = fmaf(As[r*16 + ft], ws, aV[r]);
            }
        }
    }
    const float* C = pc + s*3*FD;
    float c0 = C[tid], c1 = C[FD + tid], c2 = C[2*FD + tid];
    #pragma unroll
    for (int r = 0; r < 16; r++){
        int nd = nodes[r];
        if (nd < 0) continue;
        float sv = 0.5f * aU[r];
        float o  = sv * (c0 + c1*sv + c2*sv*sv);
        if (HAS_SC) o += aV[r];
        g_scal[nd*FD + tid] = o;
        if (!HAS_SC) g_agg[nd*FD + tid] = 0.0f;   // prep for layer 1
    }
}

// ---------------- readouts ---------------------------------------------------
__global__ void k_ro0(const float* __restrict__ ro0, float* __restrict__ out){
    int w = (blockIdx.x*blockDim.x + threadIdx.x) >> 5;
    int lane = threadIdx.x & 31;
    if (w >= NN) return;
    float sacc = 0.0f;
    #pragma unroll
    for (int k = 0; k < 4; k++){
        int f = lane + 32*k;
        sacc = fmaf(g_scal[w*FD + f], ro0[f], sacc);
    }
    #pragma unroll
    for (int o = 16; o; o >>= 1) sacc += __shfl_xor_sync(0xffffffffu, sacc, o);
    if (lane == 0) out[w*2 + 0] = sacc;
}

__global__ void k_ro1(const float* __restrict__ W1, const float* __restrict__ W2,
                      float* __restrict__ out){
    int w = (blockIdx.x*blockDim.x + threadIdx.x) >> 5;
    int lane = threadIdx.x & 31;
    if (w >= NN) return;
    float sc[4];
    #pragma unroll
    for (int k = 0; k < 4; k++) sc[k] = g_scal[w*FD + lane + 32*k];
    float acc = 0.0f;
    #pragma unroll
    for (int j = 0; j < 16; j++){
        float p = 0.0f;
        #pragma unroll
        for (int k = 0; k < 4; k++)
            p = fmaf(sc[k], W1[(lane + 32*k)*16 + j], p);
        #pragma unroll
        for (int o = 16; o; o >>= 1) p += __shfl_xor_sync(0xffffffffu, p, o);
        float h = __fdividef(p, 1.0f + __expf(-p));
        acc = fmaf(h, W2[j], acc);
    }
    if (lane == 0) out[w*2 + 1] = acc;
}

// ---------------- launcher ---------------------------------------------------
extern "C" void kernel_launch(void* const* d_in, const int* in_sizes, int n_in,
                              void* d_out, int out_size)
{
    const float* vectors = (const float*)d_in[0];
    const int*   spec    = (const int*)  d_in[1];
    const int*   snd     = (const int*)  d_in[2];
    const int*   rcv     = (const int*)  d_in[3];
    const float* emb     = (const float*)d_in[4];
    const float* rW1     = (const float*)d_in[5];
    const float* rb1     = (const float*)d_in[6];
    const float* rW2     = (const float*)d_in[7];
    const float* linW    = (const float*)d_in[8];
    const float* pc      = (const float*)d_in[9];
    const float* scW     = (const float*)d_in[10];
    const float* ro0     = (const float*)d_in[11];
    const float* ro1W1   = (const float*)d_in[12];
    const float* ro1W2   = (const float*)d_in[13];
    float* out = (float*)d_out;

    const int LAYER_LIN  = NSPEC * 4 * FD * FD;
    const int LAYER_PC   = NSPEC * 3 * FD;

    ull*   w2d_ptr;  cudaGetSymbolAddress((void**)&w2d_ptr, g_w2d);
    float* h_ptr;    cudaGetSymbolAddress((void**)&h_ptr,   g_h);

    int nchunks = NN/16 + NSPEC;

    k_h<<<NEB/4, 128>>>(vectors, rW1, rb1);                          // 1
    k_init<<<(NN*FD + 255)/256, 256>>>(spec, emb);                   // 2
    k_w2t<<<64, 256>>>(rW2);                                         // 3
    k_edge<<<NEB/8, 256>>>(w2d_ptr, snd, rcv, h_ptr);                // 4  layer 0 (profiled)
    k_b2<<<1, 32>>>();                                               // 5
    k_b4<<<(NN + 255)/256, 256>>>(spec);                             // 6
    k_node<false><<<nchunks, 128>>>(linW, linW, pc);                 // 7 (+agg zero)
    k_ro0<<<(NN*32 + 255)/256, 256>>>(ro0, out);                     // 8
    k_edge<<<NEB/8, 256>>>(w2d_ptr + NHID*FD, snd, rcv,
                           h_ptr + (size_t)NEB*NHID*32);             // 9  layer 1
    k_node<true><<<nchunks, 128>>>(linW + LAYER_LIN, scW + LAYER_LIN,
                                   pc + LAYER_PC);                   // 10
    k_ro1<<<(NN*32 + 255)/256, 256>>>(ro1W1, ro1W2, out);            // 11
}